// round 16
// baseline (speedup 1.0000x reference)
#include <cuda_runtime.h>
#include <cuda_bf16.h>
#include <math.h>

// Problem constants (fixed by the dataset)
#define MAXN 100000
#define MAXE 1600000
#define F 32            // F_IN == F_OUT == 32
#define SCAN_B 256      // elements per scan block

// Scratch (static device globals; no allocation allowed)
__device__ float d_deg[MAXN];        // degree -> dinv (after k_scan23)
__device__ int   d_cnt[MAXN];        // counts -> cursor -> inclusive prefix
__device__ int   d_bsum[1024];       // per-block aggregate sums for the scan
__device__ int2  d_edge[MAXE];       // CSR-by-dst: {src, coef bits} interleaved

// ---------------------------------------------------------------------------
// f32x2 packed-pipe helpers (sm_103a dual-fp32)
// ---------------------------------------------------------------------------
__device__ __forceinline__ unsigned long long pk2(float lo, float hi) {
    unsigned long long r;
    asm("mov.b64 %0, {%1, %2};" : "=l"(r) : "f"(lo), "f"(hi));
    return r;
}
__device__ __forceinline__ void upk2(unsigned long long v, float& lo, float& hi) {
    asm("mov.b64 {%0, %1}, %2;" : "=f"(lo), "=f"(hi) : "l"(v));
}
__device__ __forceinline__ unsigned long long fma2(unsigned long long a,
                                                   unsigned long long b,
                                                   unsigned long long c) {
    unsigned long long d;
    asm("fma.rn.f32x2 %0, %1, %2, %3;" : "=l"(d) : "l"(a), "l"(b), "l"(c));
    return d;
}

// ---------------------------------------------------------------------------
// Per-block edge_index dtype detect (warp 0 ballot -> shared broadcast).
// Under int64 interpretation of int32 data, a probed value is >= 2^32
// whenever the odd word is nonzero; 64 probes -> certain.
// ---------------------------------------------------------------------------
__device__ __forceinline__ int block_detect_idx64(const void* __restrict__ ei,
                                                  int E, int n, int* s64) {
    if (threadIdx.x < 32) {
        const long long* p = (const long long*)ei;
        int lane = threadIdx.x;
        long long a = p[lane];
        long long b = p[E + lane];
        int bad = (a < 0 || a >= n || b < 0 || b >= n) ? 1 : 0;
        unsigned m = __ballot_sync(0xffffffffu, bad);
        if (lane == 0) *s64 = (m == 0u) ? 1 : 0;
    }
    __syncthreads();
    return *s64;
}

// ---------------------------------------------------------------------------
// Shared edge decode
// ---------------------------------------------------------------------------
__device__ __forceinline__ void decode_edge(const void* __restrict__ ei,
                                            const float* __restrict__ ew,
                                            int idx64, int E, int n, int e,
                                            int& s, int& d, float& w) {
    if (idx64) {
        const long long* p = (const long long*)ei;
        s = (int)p[e];
        d = (int)p[E + e];
    } else {
        const int* p = (const int*)ei;
        s = p[e];
        d = p[E + e];
    }
    w = ew[e];
    if ((unsigned)s >= (unsigned)n || (unsigned)d >= (unsigned)n) {
        s = 0; d = 0; w = 0.0f;
    }
    if (s == d) w = 0.0f;
}

// ---------------------------------------------------------------------------
// K1: count pass:  deg[src] += w  and  cnt[dst] += 1 for live edges
// (d_deg / d_cnt pre-zeroed by cudaMemsetAsync)
// ---------------------------------------------------------------------------
__global__ void k_prep(const void* __restrict__ ei,
                       const float* __restrict__ ew, int E, int n) {
    __shared__ int s64;
    int idx64 = block_detect_idx64(ei, E, n, &s64);
    int e = blockIdx.x * blockDim.x + threadIdx.x;
    if (e >= E) return;
    int s, d; float w;
    decode_edge(ei, ew, idx64, E, n, e, s, d, w);
    if (w != 0.0f) {
        atomicAdd(&d_deg[s], w);
        atomicAdd(&d_cnt[d], 1);
    }
}

// ---------------------------------------------------------------------------
// K2a: per-block aggregate sums of cnt (SCAN_B elements per block)
// ---------------------------------------------------------------------------
__global__ void k_scan1(int n) {
    __shared__ int wsum[SCAN_B / 32];
    int t = threadIdx.x;
    int i = blockIdx.x * SCAN_B + t;
    int v = (i < n) ? d_cnt[i] : 0;
#pragma unroll
    for (int off = 16; off > 0; off >>= 1)
        v += __shfl_down_sync(0xffffffffu, v, off);
    if ((t & 31) == 0) wsum[t >> 5] = v;
    __syncthreads();
    if (t == 0) {
        int s = 0;
#pragma unroll
        for (int j = 0; j < SCAN_B / 32; j++) s += wsum[j];
        d_bsum[blockIdx.x] = s;
    }
}

// ---------------------------------------------------------------------------
// K2b: per-block exclusive scan -> cursor in d_cnt.  Each block computes its
// own base by summing all preceding block aggregates.  Also deg -> dinv.
// ---------------------------------------------------------------------------
__global__ void k_scan23(int n) {
    __shared__ int wsum[SCAN_B / 32];
    __shared__ int sred[SCAN_B / 32];
    __shared__ int sbase;
    int t = threadIdx.x;
    int lane = t & 31, w = t >> 5;

    // ---- base = sum of d_bsum[0 .. blockIdx.x) ----
    int pre = 0;
    for (int c = t; c < blockIdx.x; c += SCAN_B) pre += d_bsum[c];
#pragma unroll
    for (int off = 16; off > 0; off >>= 1)
        pre += __shfl_down_sync(0xffffffffu, pre, off);
    if (lane == 0) sred[w] = pre;
    __syncthreads();
    if (t == 0) {
        int b = 0;
#pragma unroll
        for (int j = 0; j < SCAN_B / 32; j++) b += sred[j];
        sbase = b;
    }
    __syncthreads();

    // ---- local exclusive scan of this block's SCAN_B counts ----
    int i = blockIdx.x * SCAN_B + t;
    int v = (i < n) ? d_cnt[i] : 0;
    int s = v;
#pragma unroll
    for (int off = 1; off < 32; off <<= 1) {
        int u = __shfl_up_sync(0xffffffffu, s, off);
        if (lane >= off) s += u;
    }
    if (lane == 31) wsum[w] = s;
    __syncthreads();
    if (t == 0) {
        int run = 0;
#pragma unroll
        for (int j = 0; j < SCAN_B / 32; j++) {
            int c = wsum[j]; wsum[j] = run; run += c;
        }
    }
    __syncthreads();
    if (i < n) {
        d_cnt[i] = (s - v) + wsum[w] + sbase;
        float dg = d_deg[i];
        d_deg[i] = (dg > 0.0f) ? rsqrtf(dg) : 0.0f;
    }
}

// ---------------------------------------------------------------------------
// K3: reorder edges into CSR-by-dst as int2 {src, coefbits} (one STG.64).
//     coef = -dinv[src] * w * dinv[dst]   (d_deg holds dinv)
// ---------------------------------------------------------------------------
__global__ void k_reorder(const void* __restrict__ ei,
                          const float* __restrict__ ew, int E, int n) {
    __shared__ int s64;
    int idx64 = block_detect_idx64(ei, E, n, &s64);
    int e = blockIdx.x * blockDim.x + threadIdx.x;
    if (e >= E) return;
    int s, d; float w;
    decode_edge(ei, ew, idx64, E, n, e, s, d, w);
    if (w == 0.0f) return;
    float c = -d_deg[s] * w * d_deg[d];
    int pos = atomicAdd(&d_cnt[d], 1);
    d_edge[pos] = make_int2(s, __float_as_int(c));
}

// ---------------------------------------------------------------------------
// K4: fused gather (tx1 in registers) + gates + output.
// One warp handles 4 nodes; lane = output feature. Gather inner loop is
// unrolled x4 with zero-padded lanes (4 independent LDGs in flight);
// edge metadata is one LDG.64 per lane. Gate matvecs use fma.rn.f32x2.
// ---------------------------------------------------------------------------
__global__ void k_gather_gates(const float* __restrict__ x,
                               const float* __restrict__ Wx,
                               const float* __restrict__ bx,
                               const float* __restrict__ bh,
                               const float* __restrict__ wc,
                               const float* __restrict__ bgate,
                               const float* __restrict__ linw,
                               const float* __restrict__ linb,
                               float* __restrict__ out, int n) {
    __shared__ float sW[6][F * F];   // Wi0, Wi1, Wc0, Wc1, Wo0, Wo1
    __shared__ float sBi[F], sBc[F], sBo[F], sWc2[F], sLw[F];
    __shared__ float sLb;

    int tid = threadIdx.x;
    for (int i = tid; i < F * F; i += blockDim.x) {
        sW[0][i] = Wx[0 * F * F + i];   // gate i, k=0
        sW[1][i] = Wx[1 * F * F + i];   // gate i, k=1
        sW[2][i] = Wx[4 * F * F + i];   // gate c, k=0
        sW[3][i] = Wx[5 * F * F + i];   // gate c, k=1
        sW[4][i] = Wx[6 * F * F + i];   // gate o, k=0
        sW[5][i] = Wx[7 * F * F + i];   // gate o, k=1
    }
    if (tid < F) {
        sBi[tid]  = bx[0 * F + tid] + bh[0 * F + tid] + bgate[0 * F + tid];
        sBc[tid]  = bx[2 * F + tid] + bh[2 * F + tid] + bgate[2 * F + tid];
        sBo[tid]  = bx[3 * F + tid] + bh[3 * F + tid] + bgate[3 * F + tid];
        sWc2[tid] = wc[2 * F + tid];
        sLw[tid]  = linw[tid];
        if (tid == 0) sLb = linb[0];
    }
    __syncthreads();

    int warp = tid >> 5;
    int lane = tid & 31;
    int base = (blockIdx.x * (blockDim.x >> 5) + warp) * 4;
    if (base >= n) return;

    // -------- gather phase: tx1 for 4 nodes into registers --------
    float xr[4], tr[4];
#pragma unroll
    for (int i = 0; i < 4; i++) {
        int nd = base + i;
        float acc = 0.0f, xv = 0.0f;
        if (nd < n) {                       // warp-uniform condition
            xv = x[nd * F + lane];
            int st = nd ? d_cnt[nd - 1] : 0;
            int en = d_cnt[nd];
            for (int b0 = st; b0 < en; b0 += 32) {
                int j = b0 + lane;
                int   sj = 0;
                float cj = 0.0f;
                if (j < en) { int2 ed = d_edge[j]; sj = ed.x; cj = __int_as_float(ed.y); }
                int mm = (min(32, en - b0) + 3) & ~3;
                for (int k = 0; k < mm; k += 4) {
                    int   s0 = __shfl_sync(0xffffffffu, sj, k);
                    int   s1 = __shfl_sync(0xffffffffu, sj, k + 1);
                    int   s2 = __shfl_sync(0xffffffffu, sj, k + 2);
                    int   s3 = __shfl_sync(0xffffffffu, sj, k + 3);
                    float c0 = __shfl_sync(0xffffffffu, cj, k);
                    float c1 = __shfl_sync(0xffffffffu, cj, k + 1);
                    float c2 = __shfl_sync(0xffffffffu, cj, k + 2);
                    float c3 = __shfl_sync(0xffffffffu, cj, k + 3);
                    float v0 = __ldg(&x[s0 * F + lane]);
                    float v1 = __ldg(&x[s1 * F + lane]);
                    float v2 = __ldg(&x[s2 * F + lane]);
                    float v3 = __ldg(&x[s3 * F + lane]);
                    acc += c0 * v0 + c1 * v1 + c2 * v2 + c3 * v3;
                }
            }
        }
        xr[i] = xv;
        tr[i] = acc;
    }

    // -------- gate phase: packed f32x2, 2 nodes per instruction --------
    float bi = sBi[lane], bc = sBc[lane], bo = sBo[lane];
    unsigned long long ai01 = pk2(bi, bi), ai23 = pk2(bi, bi);
    unsigned long long ac01 = pk2(bc, bc), ac23 = pk2(bc, bc);
    unsigned long long ao01 = pk2(bo, bo), ao23 = pk2(bo, bo);

#pragma unroll
    for (int f = 0; f < F; f++) {
        float w0 = sW[0][f * F + lane];
        float w1 = sW[1][f * F + lane];
        float w2 = sW[2][f * F + lane];
        float w3 = sW[3][f * F + lane];
        float w4 = sW[4][f * F + lane];
        float w5 = sW[5][f * F + lane];
        float xf0 = __shfl_sync(0xffffffffu, xr[0], f);
        float xf1 = __shfl_sync(0xffffffffu, xr[1], f);
        float xf2 = __shfl_sync(0xffffffffu, xr[2], f);
        float xf3 = __shfl_sync(0xffffffffu, xr[3], f);
        float tf0 = __shfl_sync(0xffffffffu, tr[0], f);
        float tf1 = __shfl_sync(0xffffffffu, tr[1], f);
        float tf2 = __shfl_sync(0xffffffffu, tr[2], f);
        float tf3 = __shfl_sync(0xffffffffu, tr[3], f);
        unsigned long long x01 = pk2(xf0, xf1), x23 = pk2(xf2, xf3);
        unsigned long long t01 = pk2(tf0, tf1), t23 = pk2(tf2, tf3);
        unsigned long long W0 = pk2(w0, w0), W1 = pk2(w1, w1);
        unsigned long long W2 = pk2(w2, w2), W3 = pk2(w3, w3);
        unsigned long long W4 = pk2(w4, w4), W5 = pk2(w5, w5);
        ai01 = fma2(x01, W0, fma2(t01, W1, ai01));
        ai23 = fma2(x23, W0, fma2(t23, W1, ai23));
        ac01 = fma2(x01, W2, fma2(t01, W3, ac01));
        ac23 = fma2(x23, W2, fma2(t23, W3, ac23));
        ao01 = fma2(x01, W4, fma2(t01, W5, ao01));
        ao23 = fma2(x23, W4, fma2(t23, W5, ao23));
    }

    float ai[4], ac[4], ao[4];
    upk2(ai01, ai[0], ai[1]); upk2(ai23, ai[2], ai[3]);
    upk2(ac01, ac[0], ac[1]); upk2(ac23, ac[2], ac[3]);
    upk2(ao01, ao[0], ao[1]); upk2(ao23, ao[2], ao[3]);

    float wcl = sWc2[lane], lwl = sLw[lane], lb = sLb;
#pragma unroll
    for (int i = 0; i < 4; i++) {
        int nd = base + i;
        if (nd >= n) break;                  // warp-uniform
        float I = 1.0f / (1.0f + __expf(-ai[i]));
        float T = tanhf(ac[i]);
        float C = I * T;
        float O = 1.0f / (1.0f + __expf(-(ao[i] + wcl * C)));
        float H = O * tanhf(C);
        float r = fmaxf(H, 0.0f) * lwl;
#pragma unroll
        for (int off = 16; off > 0; off >>= 1)
            r += __shfl_xor_sync(0xffffffffu, r, off);
        if (lane == 0) out[nd] = r + lb;
    }
}

// ---------------------------------------------------------------------------
extern "C" void kernel_launch(void* const* d_in, const int* in_sizes, int n_in,
                              void* d_out, int out_size) {
    const float* x     = (const float*)d_in[0];
    const void*  ei    = d_in[1];
    const float* ew    = (const float*)d_in[2];
    const float* Wx    = (const float*)d_in[3];
    const float* bx    = (const float*)d_in[4];
    // d_in[5] = Wh (dead: H_prev == 0)
    const float* bh    = (const float*)d_in[6];
    const float* wc    = (const float*)d_in[7];
    const float* bgate = (const float*)d_in[8];
    const float* linw  = (const float*)d_in[9];
    const float* linb  = (const float*)d_in[10];
    float*       out   = (float*)d_out;

    const int N = in_sizes[0] / F;
    const int E = in_sizes[2];

    const int B  = 256;
    const int NB = (N + SCAN_B - 1) / SCAN_B;   // scan blocks (<=1024)

    // Zero deg/cnt via memset nodes (not kernel launches)
    static void* p_deg = nullptr;
    static void* p_cnt = nullptr;
    if (!p_deg) {
        cudaGetSymbolAddress(&p_deg, d_deg);
        cudaGetSymbolAddress(&p_cnt, d_cnt);
    }
    cudaMemsetAsync(p_deg, 0, N * sizeof(float));
    cudaMemsetAsync(p_cnt, 0, N * sizeof(int));

    k_prep<<<(E + B - 1) / B, B>>>(ei, ew, E, N);
    k_scan1<<<NB, SCAN_B>>>(N);
    k_scan23<<<NB, SCAN_B>>>(N);
    k_reorder<<<(E + B - 1) / B, B>>>(ei, ew, E, N);
    // 8 warps/block, 4 nodes/warp -> 32 nodes per block
    k_gather_gates<<<(N + 31) / 32, B>>>(x, Wx, bx, bh, wc, bgate, linw, linb,
                                         out, N);
}

// round 17
// speedup vs baseline: 1.0474x; 1.0474x over previous
#include <cuda_runtime.h>
#include <cuda_bf16.h>
#include <math.h>

// Problem constants (fixed by the dataset)
#define MAXN 100000
#define MAXE 1600000
#define F 32            // F_IN == F_OUT == 32
#define SCAN_B 256      // elements per scan block

// Scratch (static device globals; no allocation allowed)
__device__ int   d_idx64;            // 1 if edge_index is int64, 0 if int32
__device__ float d_deg[MAXN];        // degree -> dinv (after k_scan23)
__device__ int   d_cnt[MAXN];        // in-degree counts (preserved)
__device__ int   d_off[MAXN + 1];    // exclusive prefix offsets (CSR row ptr)
__device__ int   d_bsum[1024];       // per-block aggregate sums for the scan
__device__ int4  d_stage[MAXE];      // {src, dst, w bits, rank} staged in prep
__device__ int2  d_edge[MAXE];       // CSR-by-dst: {src, dinv[s]*w bits}

// ---------------------------------------------------------------------------
// f32x2 packed-pipe helpers (sm_103a dual-fp32)
// ---------------------------------------------------------------------------
__device__ __forceinline__ unsigned long long pk2(float lo, float hi) {
    unsigned long long r;
    asm("mov.b64 %0, {%1, %2};" : "=l"(r) : "f"(lo), "f"(hi));
    return r;
}
__device__ __forceinline__ void upk2(unsigned long long v, float& lo, float& hi) {
    asm("mov.b64 {%0, %1}, %2;" : "=f"(lo), "=f"(hi) : "l"(v));
}
__device__ __forceinline__ unsigned long long fma2(unsigned long long a,
                                                   unsigned long long b,
                                                   unsigned long long c) {
    unsigned long long d;
    asm("fma.rn.f32x2 %0, %1, %2, %3;" : "=l"(d) : "l"(a), "l"(b), "l"(c));
    return d;
}

// ---------------------------------------------------------------------------
// K0: zero deg/cnt; block 0, warp 0 additionally detects edge_index dtype.
// ---------------------------------------------------------------------------
__global__ void k_init(const void* __restrict__ ei, int E, int n) {
    int i = blockIdx.x * blockDim.x + threadIdx.x;
    if (i < n) { d_deg[i] = 0.0f; d_cnt[i] = 0; }
    if (blockIdx.x == 0 && threadIdx.x < 32) {
        const long long* p = (const long long*)ei;
        int lane = threadIdx.x;
        long long a = p[lane];
        long long b = p[E + lane];
        int bad = (a < 0 || a >= n || b < 0 || b >= n) ? 1 : 0;
        unsigned m = __ballot_sync(0xffffffffu, bad);
        if (lane == 0) d_idx64 = (m == 0u) ? 1 : 0;
    }
}

// ---------------------------------------------------------------------------
// K1: decode + count + stage.  rank comes FREE from the cnt atomic's return.
//   stage[e] = {src, dst, w bits, rank}
// ---------------------------------------------------------------------------
__global__ void k_prep(const void* __restrict__ ei,
                       const float* __restrict__ ew, int E, int n) {
    int e = blockIdx.x * blockDim.x + threadIdx.x;
    if (e >= E) return;
    int s, d;
    if (d_idx64) {
        const long long* p = (const long long*)ei;
        s = (int)p[e];
        d = (int)p[E + e];
    } else {
        const int* p = (const int*)ei;
        s = p[e];
        d = p[E + e];
    }
    float w = ew[e];
    if ((unsigned)s >= (unsigned)n || (unsigned)d >= (unsigned)n) {
        s = 0; d = 0; w = 0.0f;
    }
    if (s == d) w = 0.0f;
    int rank = 0;
    if (w != 0.0f) {
        atomicAdd(&d_deg[s], w);
        rank = atomicAdd(&d_cnt[d], 1);
    }
    d_stage[e] = make_int4(s, d, __float_as_int(w), rank);
}

// ---------------------------------------------------------------------------
// K2a: per-block aggregate sums of cnt (SCAN_B elements per block)
// ---------------------------------------------------------------------------
__global__ void k_scan1(int n) {
    __shared__ int wsum[SCAN_B / 32];
    int t = threadIdx.x;
    int i = blockIdx.x * SCAN_B + t;
    int v = (i < n) ? d_cnt[i] : 0;
#pragma unroll
    for (int off = 16; off > 0; off >>= 1)
        v += __shfl_down_sync(0xffffffffu, v, off);
    if ((t & 31) == 0) wsum[t >> 5] = v;
    __syncthreads();
    if (t == 0) {
        int s = 0;
#pragma unroll
        for (int j = 0; j < SCAN_B / 32; j++) s += wsum[j];
        d_bsum[blockIdx.x] = s;
    }
}

// ---------------------------------------------------------------------------
// K2b: per-block scan -> CSR row pointers in d_off (d_off[i+1] = inclusive
// prefix; d_off[0] = 0).  Each block computes its base by summing preceding
// block aggregates.  Also deg -> dinv (fused).
// ---------------------------------------------------------------------------
__global__ void k_scan23(int n) {
    __shared__ int wsum[SCAN_B / 32];
    __shared__ int sred[SCAN_B / 32];
    __shared__ int sbase;
    int t = threadIdx.x;
    int lane = t & 31, w = t >> 5;

    // ---- base = sum of d_bsum[0 .. blockIdx.x) ----
    int pre = 0;
    for (int c = t; c < blockIdx.x; c += SCAN_B) pre += d_bsum[c];
#pragma unroll
    for (int off = 16; off > 0; off >>= 1)
        pre += __shfl_down_sync(0xffffffffu, pre, off);
    if (lane == 0) sred[w] = pre;
    __syncthreads();
    if (t == 0) {
        int b = 0;
#pragma unroll
        for (int j = 0; j < SCAN_B / 32; j++) b += sred[j];
        sbase = b;
    }
    __syncthreads();

    // ---- local inclusive scan of this block's SCAN_B counts ----
    int i = blockIdx.x * SCAN_B + t;
    int v = (i < n) ? d_cnt[i] : 0;
    int s = v;
#pragma unroll
    for (int off = 1; off < 32; off <<= 1) {
        int u = __shfl_up_sync(0xffffffffu, s, off);
        if (lane >= off) s += u;
    }
    if (lane == 31) wsum[w] = s;
    __syncthreads();
    if (t == 0) {
        int run = 0;
#pragma unroll
        for (int j = 0; j < SCAN_B / 32; j++) {
            int c = wsum[j]; wsum[j] = run; run += c;
        }
    }
    __syncthreads();
    if (i < n) {
        d_off[i + 1] = s + wsum[w] + sbase;       // inclusive prefix
        if (i == 0) d_off[0] = 0;
        float dg = d_deg[i];
        d_deg[i] = (dg > 0.0f) ? rsqrtf(dg) : 0.0f;
    }
}

// ---------------------------------------------------------------------------
// K3: place edges into CSR-by-dst — NO atomics, coalesced int4 read.
//   pos = off[dst] + rank;  coef = dinv[src]*w   (the -dinv[dst] factor is
//   applied per-node in the gather).
// ---------------------------------------------------------------------------
__global__ void k_reorder(int E) {
    int e = blockIdx.x * blockDim.x + threadIdx.x;
    if (e >= E) return;
    int4 ed = d_stage[e];
    float w = __int_as_float(ed.z);
    if (w == 0.0f) return;
    float c = d_deg[ed.x] * w;                  // dinv[src] * w
    int pos = d_off[ed.y] + ed.w;
    d_edge[pos] = make_int2(ed.x, __float_as_int(c));
}

// ---------------------------------------------------------------------------
// K4: fused gather (tx1 in registers) + gates + output.
// One warp handles 4 nodes; lane = output feature. Row bounds from d_off
// (branchless). Per-node factor -dinv[nd] applied once after the row sum.
// Gate matvecs use fma.rn.f32x2 (2 nodes per instruction).
// ---------------------------------------------------------------------------
__global__ void k_gather_gates(const float* __restrict__ x,
                               const float* __restrict__ Wx,
                               const float* __restrict__ bx,
                               const float* __restrict__ bh,
                               const float* __restrict__ wc,
                               const float* __restrict__ bgate,
                               const float* __restrict__ linw,
                               const float* __restrict__ linb,
                               float* __restrict__ out, int n) {
    __shared__ float sW[6][F * F];   // Wi0, Wi1, Wc0, Wc1, Wo0, Wo1
    __shared__ float sBi[F], sBc[F], sBo[F], sWc2[F], sLw[F];
    __shared__ float sLb;

    int tid = threadIdx.x;
    for (int i = tid; i < F * F; i += blockDim.x) {
        sW[0][i] = Wx[0 * F * F + i];   // gate i, k=0
        sW[1][i] = Wx[1 * F * F + i];   // gate i, k=1
        sW[2][i] = Wx[4 * F * F + i];   // gate c, k=0
        sW[3][i] = Wx[5 * F * F + i];   // gate c, k=1
        sW[4][i] = Wx[6 * F * F + i];   // gate o, k=0
        sW[5][i] = Wx[7 * F * F + i];   // gate o, k=1
    }
    if (tid < F) {
        sBi[tid]  = bx[0 * F + tid] + bh[0 * F + tid] + bgate[0 * F + tid];
        sBc[tid]  = bx[2 * F + tid] + bh[2 * F + tid] + bgate[2 * F + tid];
        sBo[tid]  = bx[3 * F + tid] + bh[3 * F + tid] + bgate[3 * F + tid];
        sWc2[tid] = wc[2 * F + tid];
        sLw[tid]  = linw[tid];
        if (tid == 0) sLb = linb[0];
    }
    __syncthreads();

    int warp = tid >> 5;
    int lane = tid & 31;
    int base = (blockIdx.x * (blockDim.x >> 5) + warp) * 4;
    if (base >= n) return;

    // -------- gather phase: tx1 for 4 nodes into registers --------
    float xr[4], tr[4];
#pragma unroll
    for (int i = 0; i < 4; i++) {
        int nd = base + i;
        float acc = 0.0f, xv = 0.0f;
        if (nd < n) {                       // warp-uniform condition
            xv = x[nd * F + lane];
            int st = d_off[nd];
            int en = d_off[nd + 1];
            for (int b0 = st; b0 < en; b0 += 32) {
                int j = b0 + lane;
                int   sj = 0;
                float cj = 0.0f;
                if (j < en) { int2 ed = d_edge[j]; sj = ed.x; cj = __int_as_float(ed.y); }
                int mm = (min(32, en - b0) + 3) & ~3;
                for (int k = 0; k < mm; k += 4) {
                    int   s0 = __shfl_sync(0xffffffffu, sj, k);
                    int   s1 = __shfl_sync(0xffffffffu, sj, k + 1);
                    int   s2 = __shfl_sync(0xffffffffu, sj, k + 2);
                    int   s3 = __shfl_sync(0xffffffffu, sj, k + 3);
                    float c0 = __shfl_sync(0xffffffffu, cj, k);
                    float c1 = __shfl_sync(0xffffffffu, cj, k + 1);
                    float c2 = __shfl_sync(0xffffffffu, cj, k + 2);
                    float c3 = __shfl_sync(0xffffffffu, cj, k + 3);
                    float v0 = __ldg(&x[s0 * F + lane]);
                    float v1 = __ldg(&x[s1 * F + lane]);
                    float v2 = __ldg(&x[s2 * F + lane]);
                    float v3 = __ldg(&x[s3 * F + lane]);
                    acc += c0 * v0 + c1 * v1 + c2 * v2 + c3 * v3;
                }
            }
            acc *= -d_deg[nd];              // apply -dinv[dst] once per node
        }
        xr[i] = xv;
        tr[i] = acc;
    }

    // -------- gate phase: packed f32x2, 2 nodes per instruction --------
    float bi = sBi[lane], bc = sBc[lane], bo = sBo[lane];
    unsigned long long ai01 = pk2(bi, bi), ai23 = pk2(bi, bi);
    unsigned long long ac01 = pk2(bc, bc), ac23 = pk2(bc, bc);
    unsigned long long ao01 = pk2(bo, bo), ao23 = pk2(bo, bo);

#pragma unroll
    for (int f = 0; f < F; f++) {
        float w0 = sW[0][f * F + lane];
        float w1 = sW[1][f * F + lane];
        float w2 = sW[2][f * F + lane];
        float w3 = sW[3][f * F + lane];
        float w4 = sW[4][f * F + lane];
        float w5 = sW[5][f * F + lane];
        float xf0 = __shfl_sync(0xffffffffu, xr[0], f);
        float xf1 = __shfl_sync(0xffffffffu, xr[1], f);
        float xf2 = __shfl_sync(0xffffffffu, xr[2], f);
        float xf3 = __shfl_sync(0xffffffffu, xr[3], f);
        float tf0 = __shfl_sync(0xffffffffu, tr[0], f);
        float tf1 = __shfl_sync(0xffffffffu, tr[1], f);
        float tf2 = __shfl_sync(0xffffffffu, tr[2], f);
        float tf3 = __shfl_sync(0xffffffffu, tr[3], f);
        unsigned long long x01 = pk2(xf0, xf1), x23 = pk2(xf2, xf3);
        unsigned long long t01 = pk2(tf0, tf1), t23 = pk2(tf2, tf3);
        unsigned long long W0 = pk2(w0, w0), W1 = pk2(w1, w1);
        unsigned long long W2 = pk2(w2, w2), W3 = pk2(w3, w3);
        unsigned long long W4 = pk2(w4, w4), W5 = pk2(w5, w5);
        ai01 = fma2(x01, W0, fma2(t01, W1, ai01));
        ai23 = fma2(x23, W0, fma2(t23, W1, ai23));
        ac01 = fma2(x01, W2, fma2(t01, W3, ac01));
        ac23 = fma2(x23, W2, fma2(t23, W3, ac23));
        ao01 = fma2(x01, W4, fma2(t01, W5, ao01));
        ao23 = fma2(x23, W4, fma2(t23, W5, ao23));
    }

    float ai[4], ac[4], ao[4];
    upk2(ai01, ai[0], ai[1]); upk2(ai23, ai[2], ai[3]);
    upk2(ac01, ac[0], ac[1]); upk2(ac23, ac[2], ac[3]);
    upk2(ao01, ao[0], ao[1]); upk2(ao23, ao[2], ao[3]);

    float wcl = sWc2[lane], lwl = sLw[lane], lb = sLb;
#pragma unroll
    for (int i = 0; i < 4; i++) {
        int nd = base + i;
        if (nd >= n) break;                  // warp-uniform
        float I = 1.0f / (1.0f + __expf(-ai[i]));
        float T = tanhf(ac[i]);
        float C = I * T;
        float O = 1.0f / (1.0f + __expf(-(ao[i] + wcl * C)));
        float H = O * tanhf(C);
        float r = fmaxf(H, 0.0f) * lwl;
#pragma unroll
        for (int off = 16; off > 0; off >>= 1)
            r += __shfl_xor_sync(0xffffffffu, r, off);
        if (lane == 0) out[nd] = r + lb;
    }
}

// ---------------------------------------------------------------------------
extern "C" void kernel_launch(void* const* d_in, const int* in_sizes, int n_in,
                              void* d_out, int out_size) {
    const float* x     = (const float*)d_in[0];
    const void*  ei    = d_in[1];
    const float* ew    = (const float*)d_in[2];
    const float* Wx    = (const float*)d_in[3];
    const float* bx    = (const float*)d_in[4];
    // d_in[5] = Wh (dead: H_prev == 0)
    const float* bh    = (const float*)d_in[6];
    const float* wc    = (const float*)d_in[7];
    const float* bgate = (const float*)d_in[8];
    const float* linw  = (const float*)d_in[9];
    const float* linb  = (const float*)d_in[10];
    float*       out   = (float*)d_out;

    const int N = in_sizes[0] / F;
    const int E = in_sizes[2];

    const int B  = 256;
    const int NB = (N + SCAN_B - 1) / SCAN_B;   // scan blocks (<=1024)

    k_init<<<(N + B - 1) / B, B>>>(ei, E, N);
    k_prep<<<(E + B - 1) / B, B>>>(ei, ew, E, N);
    k_scan1<<<NB, SCAN_B>>>(N);
    k_scan23<<<NB, SCAN_B>>>(N);
    k_reorder<<<(E + B - 1) / B, B>>>(E);
    // 8 warps/block, 4 nodes/warp -> 32 nodes per block
    k_gather_gates<<<(N + 31) / 32, B>>>(x, Wx, bx, bh, wc, bgate, linw, linb,
                                         out, N);
}